// round 2
// baseline (speedup 1.0000x reference)
#include <cuda_runtime.h>
#include <math.h>

// Problem constants
#define B_SZ   16
#define T_SZ   1024
#define C_SZ   256
#define H_SZ   8
#define D_SZ   32
#define M_ROWS (B_SZ * T_SZ)      // 16384
#define FF_SZ  (4 * C_SZ)         // 1024

// Scratch (allocation-free rule: __device__ globals)
__device__ float g_h  [M_ROWS * C_SZ];
__device__ float g_q  [M_ROWS * C_SZ];   // [B,H,T,D]
__device__ float g_k  [M_ROWS * C_SZ];
__device__ float g_v  [M_ROWS * C_SZ];
__device__ float g_att[M_ROWS * C_SZ];   // [B,T,C] (heads concat)
__device__ float g_x1 [M_ROWS * C_SZ];
__device__ float g_h2 [M_ROWS * C_SZ];
__device__ float g_f1 [M_ROWS * FF_SZ];

// ---------------------------------------------------------------------------
// LayerNorm: one warp per row of 256 floats (8 floats / lane via 2x float4)
// ---------------------------------------------------------------------------
__global__ void ln_kernel(const float* __restrict__ x,
                          const float* __restrict__ g,
                          const float* __restrict__ b,
                          float* __restrict__ out) {
    int warp = threadIdx.x >> 5;
    int lane = threadIdx.x & 31;
    int row  = blockIdx.x * 8 + warp;

    const float4* xr = (const float4*)(x + (size_t)row * C_SZ);
    float4 v0 = xr[lane];
    float4 v1 = xr[lane + 32];

    float s  = v0.x + v0.y + v0.z + v0.w + v1.x + v1.y + v1.z + v1.w;
    float ss = v0.x*v0.x + v0.y*v0.y + v0.z*v0.z + v0.w*v0.w
             + v1.x*v1.x + v1.y*v1.y + v1.z*v1.z + v1.w*v1.w;

    #pragma unroll
    for (int o = 16; o; o >>= 1) {
        s  += __shfl_xor_sync(0xFFFFFFFFu, s,  o);
        ss += __shfl_xor_sync(0xFFFFFFFFu, ss, o);
    }
    float mu  = s * (1.0f / C_SZ);
    float var = ss * (1.0f / C_SZ) - mu * mu;
    float inv = rsqrtf(var + 1e-5f);

    const float4* gr = (const float4*)g;
    const float4* br = (const float4*)b;
    float4 g0 = gr[lane], g1 = gr[lane + 32];
    float4 b0 = br[lane], b1 = br[lane + 32];

    float4 o0, o1;
    o0.x = (v0.x - mu) * inv * g0.x + b0.x;
    o0.y = (v0.y - mu) * inv * g0.y + b0.y;
    o0.z = (v0.z - mu) * inv * g0.z + b0.z;
    o0.w = (v0.w - mu) * inv * g0.w + b0.w;
    o1.x = (v1.x - mu) * inv * g1.x + b1.x;
    o1.y = (v1.y - mu) * inv * g1.y + b1.y;
    o1.z = (v1.z - mu) * inv * g1.z + b1.z;
    o1.w = (v1.w - mu) * inv * g1.w + b1.w;

    float4* orow = (float4*)(out + (size_t)row * C_SZ);
    orow[lane]      = o0;
    orow[lane + 32] = o1;
}

// ---------------------------------------------------------------------------
// Tiled fp32 GEMM: C[M,N] = A[M,K] @ B[K,N]   BM=128, BN=64, BK=16, 256 thr.
// MODE 0: B is (H,C,D) head weights, out scattered to [B,H,T,D]
// MODE 1: out = acc + bias + res                (attn proj)
// MODE 2: out = relu(acc + bias)               (ff1)
// MODE 3: out = acc + bias + res               (ff2, K=1024)
// ---------------------------------------------------------------------------
template <int MODE>
__global__ __launch_bounds__(256)
void gemm_kernel(const float* __restrict__ A, const float* __restrict__ B,
                 const float* __restrict__ bias, const float* __restrict__ res,
                 float* __restrict__ out, int N, int K) {
    __shared__ float As[128][17];   // padded: conflict-free broadcast reads
    __shared__ float Bs[16][64];

    int tid = threadIdx.x;
    int tx = tid & 15;        // 0..15 -> 4 output cols each
    int ty = tid >> 4;        // 0..15 -> 8 output rows each
    int m0 = blockIdx.y * 128;
    int n0 = blockIdx.x * 64;

    float acc[8][4] = {};

    for (int k0 = 0; k0 < K; k0 += 16) {
        // --- load A tile (128x16), float4 per thread x2 ---
        #pragma unroll
        for (int it = 0; it < 2; it++) {
            int idx = tid * 2 + it;          // 0..511 float4s
            int row = idx >> 2;
            int c4  = idx & 3;
            float4 av = *(const float4*)(A + (size_t)(m0 + row) * K + k0 + c4 * 4);
            As[row][c4 * 4 + 0] = av.x;
            As[row][c4 * 4 + 1] = av.y;
            As[row][c4 * 4 + 2] = av.z;
            As[row][c4 * 4 + 3] = av.w;
        }
        // --- load B tile (16x64) ---
        #pragma unroll
        for (int it = 0; it < 4; it++) {
            int r = (tid >> 6) + it * 4;     // 0..15
            int c = tid & 63;
            int kk = k0 + r;
            int n  = n0 + c;
            float bv;
            if (MODE == 0)
                bv = B[(n >> 5) * (C_SZ * D_SZ) + kk * D_SZ + (n & 31)];
            else
                bv = B[(size_t)kk * N + n];
            Bs[r][c] = bv;
        }
        __syncthreads();

        #pragma unroll
        for (int k = 0; k < 16; k++) {
            float4 b4 = *(const float4*)&Bs[k][tx * 4];
            float a_[8];
            #pragma unroll
            for (int i = 0; i < 8; i++) a_[i] = As[ty * 8 + i][k];
            #pragma unroll
            for (int i = 0; i < 8; i++) {
                acc[i][0] += a_[i] * b4.x;
                acc[i][1] += a_[i] * b4.y;
                acc[i][2] += a_[i] * b4.z;
                acc[i][3] += a_[i] * b4.w;
            }
        }
        __syncthreads();
    }

    // --- epilogue ---
    #pragma unroll
    for (int i = 0; i < 8; i++) {
        int m = m0 + ty * 8 + i;
        #pragma unroll
        for (int j = 0; j < 4; j++) {
            int n = n0 + tx * 4 + j;
            float vv = acc[i][j];
            if (MODE == 0) {
                int bb = m >> 10, t = m & 1023;
                int hh = n >> 5,  d = n & 31;
                out[(((size_t)bb * H_SZ + hh) * T_SZ + t) * D_SZ + d] = vv;
            } else if (MODE == 1 || MODE == 3) {
                out[(size_t)m * N + n] = vv + bias[n] + res[(size_t)m * N + n];
            } else { // MODE 2
                vv += bias[n];
                out[(size_t)m * N + n] = vv > 0.0f ? vv : 0.0f;
            }
        }
    }
}

// ---------------------------------------------------------------------------
// Flash attention (causal, fp32). One thread per query, 64 queries per block.
// q,k,v: [B,H,T,D].  out: [B,T,C] with heads concatenated.
// Scale is C**-0.5 = 1/16 (per reference).
// Scores are O(±4), so exp(score - m) with m>=0 never overflows -> lazy
// per-tile max rescale is safe with m initialized to 0.
// ---------------------------------------------------------------------------
__global__ __launch_bounds__(64)
void attn_kernel(const float* __restrict__ q, const float* __restrict__ k,
                 const float* __restrict__ v, float* __restrict__ out) {
    __shared__ float4 Ks[64 * 8];   // 64 keys x 32 floats
    __shared__ float4 Vs[64 * 8];

    int tid = threadIdx.x;          // 0..63 query within tile
    int qt  = blockIdx.x;           // 0..15 query tile
    int bh  = blockIdx.y;           // 0..127 (b*8+h)
    int t   = qt * 64 + tid;

    const float4* qp = (const float4*)(q + ((size_t)bh * T_SZ + t) * D_SZ);
    float4 qa[8];
    #pragma unroll
    for (int i = 0; i < 8; i++) qa[i] = qp[i];

    float4 acc[8];
    #pragma unroll
    for (int i = 0; i < 8; i++) acc[i] = make_float4(0.f, 0.f, 0.f, 0.f);
    float m_run = 0.0f, l = 0.0f;

    for (int kt = 0; kt <= qt; kt++) {
        const float4* kp = (const float4*)(k + ((size_t)bh * T_SZ + kt * 64) * D_SZ);
        const float4* vp = (const float4*)(v + ((size_t)bh * T_SZ + kt * 64) * D_SZ);
        __syncthreads();
        #pragma unroll
        for (int i = 0; i < 8; i++) {
            Ks[tid + i * 64] = kp[tid + i * 64];
            Vs[tid + i * 64] = vp[tid + i * 64];
        }
        __syncthreads();

        int smax = (kt == qt) ? tid : 63;
        float tm = m_run;
        for (int s = 0; s <= smax; s++) {
            const float4* krow = &Ks[s * 8];
            float dot = 0.0f;
            #pragma unroll
            for (int i = 0; i < 8; i++) {
                float4 kk4 = krow[i];
                dot += qa[i].x * kk4.x + qa[i].y * kk4.y
                     + qa[i].z * kk4.z + qa[i].w * kk4.w;
            }
            float sc = dot * 0.0625f;          // * C**-0.5
            tm = fmaxf(tm, sc);
            float p = __expf(sc - m_run);
            l += p;
            const float4* vrow = &Vs[s * 8];
            #pragma unroll
            for (int i = 0; i < 8; i++) {
                float4 vv = vrow[i];
                acc[i].x += p * vv.x;
                acc[i].y += p * vv.y;
                acc[i].z += p * vv.z;
                acc[i].w += p * vv.w;
            }
        }
        if (tm > m_run) {
            float corr = __expf(m_run - tm);
            l *= corr;
            #pragma unroll
            for (int i = 0; i < 8; i++) {
                acc[i].x *= corr; acc[i].y *= corr;
                acc[i].z *= corr; acc[i].w *= corr;
            }
            m_run = tm;
        }
    }

    float inv = __fdividef(1.0f, l);
    int bb = bh >> 3, hh = bh & 7;
    float4* op = (float4*)(out + ((size_t)(bb * T_SZ + t) * C_SZ + hh * D_SZ));
    #pragma unroll
    for (int i = 0; i < 8; i++) {
        float4 o;
        o.x = acc[i].x * inv; o.y = acc[i].y * inv;
        o.z = acc[i].z * inv; o.w = acc[i].w * inv;
        op[i] = o;
    }
}

// ---------------------------------------------------------------------------
extern "C" void kernel_launch(void* const* d_in, const int* in_sizes, int n_in,
                              void* d_out, int out_size) {
    (void)in_sizes; (void)n_in; (void)out_size;
    const float* x      = (const float*)d_in[0];
    const float* wq     = (const float*)d_in[1];
    const float* wk     = (const float*)d_in[2];
    const float* wv     = (const float*)d_in[3];
    const float* w_proj = (const float*)d_in[4];
    const float* b_proj = (const float*)d_in[5];
    const float* w1     = (const float*)d_in[6];
    const float* b1     = (const float*)d_in[7];
    const float* w2     = (const float*)d_in[8];
    const float* b2     = (const float*)d_in[9];
    const float* ln1_g  = (const float*)d_in[10];
    const float* ln1_b  = (const float*)d_in[11];
    const float* ln2_g  = (const float*)d_in[12];
    const float* ln2_b  = (const float*)d_in[13];
    float* out = (float*)d_out;

    float *h, *qb, *kb, *vb, *att, *x1, *h2, *f1;
    cudaGetSymbolAddress((void**)&h,   g_h);
    cudaGetSymbolAddress((void**)&qb,  g_q);
    cudaGetSymbolAddress((void**)&kb,  g_k);
    cudaGetSymbolAddress((void**)&vb,  g_v);
    cudaGetSymbolAddress((void**)&att, g_att);
    cudaGetSymbolAddress((void**)&x1,  g_x1);
    cudaGetSymbolAddress((void**)&h2,  g_h2);
    cudaGetSymbolAddress((void**)&f1,  g_f1);

    // 1. LN1
    ln_kernel<<<M_ROWS / 8, 256>>>(x, ln1_g, ln1_b, h);
    // 2. QKV projections (h @ w{q,k,v} -> [B,H,T,D])
    gemm_kernel<0><<<dim3(C_SZ / 64, M_ROWS / 128), 256>>>(h, wq, nullptr, nullptr, qb, C_SZ, C_SZ);
    gemm_kernel<0><<<dim3(C_SZ / 64, M_ROWS / 128), 256>>>(h, wk, nullptr, nullptr, kb, C_SZ, C_SZ);
    gemm_kernel<0><<<dim3(C_SZ / 64, M_ROWS / 128), 256>>>(h, wv, nullptr, nullptr, vb, C_SZ, C_SZ);
    // 3. Causal flash attention -> [B,T,C]
    attn_kernel<<<dim3(T_SZ / 64, B_SZ * H_SZ), 64>>>(qb, kb, vb, att);
    // 4. Output projection + residual
    gemm_kernel<1><<<dim3(C_SZ / 64, M_ROWS / 128), 256>>>(att, w_proj, b_proj, x, x1, C_SZ, C_SZ);
    // 5. LN2
    ln_kernel<<<M_ROWS / 8, 256>>>(x1, ln2_g, ln2_b, h2);
    // 6. FF1 + ReLU
    gemm_kernel<2><<<dim3(FF_SZ / 64, M_ROWS / 128), 256>>>(h2, w1, b1, nullptr, f1, FF_SZ, C_SZ);
    // 7. FF2 + bias + residual -> out
    gemm_kernel<3><<<dim3(C_SZ / 64, M_ROWS / 128), 256>>>(f1, w2, b2, x1, out, C_SZ, FF_SZ);
}

// round 4
// speedup vs baseline: 1.6689x; 1.6689x over previous
#include <cuda_runtime.h>
#include <cstdint>
#include <math.h>

// Problem constants
#define B_SZ   16
#define T_SZ   1024
#define C_SZ   256
#define H_SZ   8
#define D_SZ   32
#define M_ROWS (B_SZ * T_SZ)      // 16384
#define FF_SZ  (4 * C_SZ)         // 1024

// Scratch (allocation-free rule: __device__ globals)
__device__ float g_h  [M_ROWS * C_SZ];
__device__ float g_q  [M_ROWS * C_SZ];   // [B,H,T,D]
__device__ float g_k  [M_ROWS * C_SZ];
__device__ float g_v  [M_ROWS * C_SZ];
__device__ float g_att[M_ROWS * C_SZ];   // [B,T,C]
__device__ float g_x1 [M_ROWS * C_SZ];
__device__ float g_h2 [M_ROWS * C_SZ];
__device__ float g_f1 [M_ROWS * FF_SZ];
// Transposed (K-major) weights
__device__ float g_wqkvT[768 * 256];     // [n=3*256][k=256]
__device__ float g_wprojT[256 * 256];
__device__ float g_w1T  [1024 * 256];
__device__ float g_w2T  [256 * 1024];

// ---------------------------------------------------------------------------
// mma.sync tf32 helpers (plain sm_103-compatible PTX, no 'a' feature needed)
// ---------------------------------------------------------------------------
__device__ __forceinline__ uint32_t f2tf32(float x) {
    uint32_t r;
    asm("cvt.rna.tf32.f32 %0, %1;" : "=r"(r) : "f"(x));
    return r;
}
__device__ __forceinline__ void mma_tf32(float* d, const uint32_t* a, const uint32_t* b) {
    asm volatile(
        "mma.sync.aligned.m16n8k8.row.col.f32.tf32.tf32.f32 "
        "{%0,%1,%2,%3}, {%4,%5,%6,%7}, {%8,%9}, {%0,%1,%2,%3};\n"
        : "+f"(d[0]), "+f"(d[1]), "+f"(d[2]), "+f"(d[3])
        : "r"(a[0]), "r"(a[1]), "r"(a[2]), "r"(a[3]), "r"(b[0]), "r"(b[1]));
}

// ---------------------------------------------------------------------------
// LayerNorm: one warp per row of 256 floats
// ---------------------------------------------------------------------------
__global__ void ln_kernel(const float* __restrict__ x,
                          const float* __restrict__ g,
                          const float* __restrict__ b,
                          float* __restrict__ out) {
    int warp = threadIdx.x >> 5;
    int lane = threadIdx.x & 31;
    int row  = blockIdx.x * 8 + warp;

    const float4* xr = (const float4*)(x + (size_t)row * C_SZ);
    float4 v0 = xr[lane];
    float4 v1 = xr[lane + 32];

    float s  = v0.x + v0.y + v0.z + v0.w + v1.x + v1.y + v1.z + v1.w;
    float ss = v0.x*v0.x + v0.y*v0.y + v0.z*v0.z + v0.w*v0.w
             + v1.x*v1.x + v1.y*v1.y + v1.z*v1.z + v1.w*v1.w;

    #pragma unroll
    for (int o = 16; o; o >>= 1) {
        s  += __shfl_xor_sync(0xFFFFFFFFu, s,  o);
        ss += __shfl_xor_sync(0xFFFFFFFFu, ss, o);
    }
    float mu  = s * (1.0f / C_SZ);
    float var = ss * (1.0f / C_SZ) - mu * mu;
    float inv = rsqrtf(var + 1e-5f);

    const float4* gr = (const float4*)g;
    const float4* br = (const float4*)b;
    float4 g0 = gr[lane], g1 = gr[lane + 32];
    float4 b0 = br[lane], b1 = br[lane + 32];

    float4 o0, o1;
    o0.x = (v0.x - mu) * inv * g0.x + b0.x;
    o0.y = (v0.y - mu) * inv * g0.y + b0.y;
    o0.z = (v0.z - mu) * inv * g0.z + b0.z;
    o0.w = (v0.w - mu) * inv * g0.w + b0.w;
    o1.x = (v1.x - mu) * inv * g1.x + b1.x;
    o1.y = (v1.y - mu) * inv * g1.y + b1.y;
    o1.z = (v1.z - mu) * inv * g1.z + b1.z;
    o1.w = (v1.w - mu) * inv * g1.w + b1.w;

    float4* orow = (float4*)(out + (size_t)row * C_SZ);
    orow[lane]      = o0;
    orow[lane + 32] = o1;
}

// ---------------------------------------------------------------------------
// Weight transposes -> K-major [N][K]
// ---------------------------------------------------------------------------
__global__ void pack_qkv_kernel(const float* __restrict__ wq, const float* __restrict__ wk,
                                const float* __restrict__ wv, float* __restrict__ outT) {
    int idx = blockIdx.x * 256 + threadIdx.x;   // 768*256 total
    int n = idx >> 8;          // 0..767
    int k = idx & 255;
    int tsel = n >> 8;         // 0:q 1:k 2:v
    int c2 = n & 255;
    int h = c2 >> 5, d = c2 & 31;
    const float* w = (tsel == 0) ? wq : (tsel == 1) ? wk : wv;
    outT[idx] = w[h * (C_SZ * D_SZ) + k * D_SZ + d];
}

__global__ void transpose_kernel(const float* __restrict__ in, float* __restrict__ outT,
                                 int Kin, int Nin) {
    // in: [Kin][Nin] row-major; outT: [Nin][Kin]
    int idx = blockIdx.x * 256 + threadIdx.x;
    int n = idx / Kin;
    int k = idx - n * Kin;
    outT[idx] = in[(size_t)k * Nin + n];
}

// ---------------------------------------------------------------------------
// tf32 HMMA GEMM: C[M, Ntot] = A[M, K] @ BwT[Ntot, K]^T
// BM=128, BN=128, BK=16, 256 threads (8 warps, each 64x32 via m16n8k8).
// MODE 0: scatter to q/k/v [B,H,T,D]  (out,out2,out3)
// MODE 1: out = acc + bias + res
// MODE 2: out = relu(acc + bias)
// ---------------------------------------------------------------------------
#define PAD 20   // SMEM row stride in words (conflict-free for frag reads)

template <int MODE>
__global__ __launch_bounds__(256)
void gemm_tc(const float* __restrict__ A, const float* __restrict__ Bw,
             const float* __restrict__ bias, const float* __restrict__ res,
             float* __restrict__ out, float* __restrict__ out2, float* __restrict__ out3,
             int Ntot, int K) {
    __shared__ uint32_t As[128][PAD];
    __shared__ uint32_t Bs[128][PAD];

    const int tid  = threadIdx.x;
    const int wid  = tid >> 5;
    const int lane = tid & 31;
    const int g    = lane >> 2;     // group id 0..7
    const int tg   = lane & 3;      // thread-in-group
    const int wm   = wid & 1;       // 0..1 -> 64-row slab
    const int wn   = wid >> 1;      // 0..3 -> 32-col slab
    const int m0   = blockIdx.y * 128;
    const int n0   = blockIdx.x * 128;

    // Per-thread global load slots: 2 float4 for A, 2 for B per chunk
    const int lrow0 = tid >> 2;                 // 0..63
    const int lrow1 = lrow0 + 64;
    const int lc4   = (tid & 3) * 4;            // word offset 0,4,8,12

    float acc[4][4][4];
    #pragma unroll
    for (int i = 0; i < 4; i++)
        #pragma unroll
        for (int j = 0; j < 4; j++)
            #pragma unroll
            for (int r = 0; r < 4; r++) acc[i][j][r] = 0.0f;

    const int nchunks = K >> 4;

    // prologue: load chunk 0
    float4 av0 = *(const float4*)(A  + (size_t)(m0 + lrow0) * K + lc4);
    float4 av1 = *(const float4*)(A  + (size_t)(m0 + lrow1) * K + lc4);
    float4 bv0 = *(const float4*)(Bw + (size_t)(n0 + lrow0) * K + lc4);
    float4 bv1 = *(const float4*)(Bw + (size_t)(n0 + lrow1) * K + lc4);

    for (int c = 0; c < nchunks; c++) {
        __syncthreads();
        As[lrow0][lc4+0] = f2tf32(av0.x); As[lrow0][lc4+1] = f2tf32(av0.y);
        As[lrow0][lc4+2] = f2tf32(av0.z); As[lrow0][lc4+3] = f2tf32(av0.w);
        As[lrow1][lc4+0] = f2tf32(av1.x); As[lrow1][lc4+1] = f2tf32(av1.y);
        As[lrow1][lc4+2] = f2tf32(av1.z); As[lrow1][lc4+3] = f2tf32(av1.w);
        Bs[lrow0][lc4+0] = f2tf32(bv0.x); Bs[lrow0][lc4+1] = f2tf32(bv0.y);
        Bs[lrow0][lc4+2] = f2tf32(bv0.z); Bs[lrow0][lc4+3] = f2tf32(bv0.w);
        Bs[lrow1][lc4+0] = f2tf32(bv1.x); Bs[lrow1][lc4+1] = f2tf32(bv1.y);
        Bs[lrow1][lc4+2] = f2tf32(bv1.z); Bs[lrow1][lc4+3] = f2tf32(bv1.w);
        __syncthreads();

        if (c + 1 < nchunks) {
            const int k0 = (c + 1) << 4;
            av0 = *(const float4*)(A  + (size_t)(m0 + lrow0) * K + k0 + lc4);
            av1 = *(const float4*)(A  + (size_t)(m0 + lrow1) * K + k0 + lc4);
            bv0 = *(const float4*)(Bw + (size_t)(n0 + lrow0) * K + k0 + lc4);
            bv1 = *(const float4*)(Bw + (size_t)(n0 + lrow1) * K + k0 + lc4);
        }

        #pragma unroll
        for (int kk = 0; kk < 16; kk += 8) {
            uint32_t af[4][4], bf[4][2];
            #pragma unroll
            for (int i = 0; i < 4; i++) {
                int r0 = wm * 64 + i * 16 + g;
                af[i][0] = As[r0    ][kk + tg];
                af[i][1] = As[r0 + 8][kk + tg];
                af[i][2] = As[r0    ][kk + tg + 4];
                af[i][3] = As[r0 + 8][kk + tg + 4];
            }
            #pragma unroll
            for (int j = 0; j < 4; j++) {
                int n = wn * 32 + j * 8 + g;
                bf[j][0] = Bs[n][kk + tg];
                bf[j][1] = Bs[n][kk + tg + 4];
            }
            #pragma unroll
            for (int i = 0; i < 4; i++)
                #pragma unroll
                for (int j = 0; j < 4; j++)
                    mma_tf32(acc[i][j], af[i], bf[j]);
        }
    }

    // ---- epilogue: each thread owns 2-float pairs ----
    #pragma unroll
    for (int i = 0; i < 4; i++) {
        #pragma unroll
        for (int half = 0; half < 2; half++) {
            int m  = m0 + wm * 64 + i * 16 + g + half * 8;
            int bb = m >> 10, t = m & 1023;
            #pragma unroll
            for (int j = 0; j < 4; j++) {
                int col = n0 + wn * 32 + j * 8 + tg * 2;
                float2 vv = make_float2(acc[i][j][half * 2], acc[i][j][half * 2 + 1]);
                if (MODE == 0) {
                    int tsel = col >> 8;
                    int c2 = col & 255;
                    int hh = c2 >> 5, d = c2 & 31;
                    float* dst = (tsel == 0) ? out : (tsel == 1) ? out2 : out3;
                    *(float2*)(dst + (((size_t)(bb * H_SZ + hh) * T_SZ + t) * D_SZ + d)) = vv;
                } else if (MODE == 1) {
                    float2 bz = *(const float2*)(bias + col);
                    float2 rr = *(const float2*)(res + (size_t)m * Ntot + col);
                    vv.x += bz.x + rr.x; vv.y += bz.y + rr.y;
                    *(float2*)(out + (size_t)m * Ntot + col) = vv;
                } else {
                    float2 bz = *(const float2*)(bias + col);
                    vv.x = fmaxf(vv.x + bz.x, 0.0f);
                    vv.y = fmaxf(vv.y + bz.y, 0.0f);
                    *(float2*)(out + (size_t)m * Ntot + col) = vv;
                }
            }
        }
    }
}

// ---------------------------------------------------------------------------
// Flash attention (causal, fp32). One thread per query, 64 queries per block.
// ---------------------------------------------------------------------------
__global__ __launch_bounds__(64)
void attn_kernel(const float* __restrict__ q, const float* __restrict__ k,
                 const float* __restrict__ v, float* __restrict__ out) {
    __shared__ float4 Ks[64 * 8];
    __shared__ float4 Vs[64 * 8];

    int tid = threadIdx.x;
    int qt  = blockIdx.x;
    int bh  = blockIdx.y;
    int t   = qt * 64 + tid;

    const float4* qp = (const float4*)(q + ((size_t)bh * T_SZ + t) * D_SZ);
    float4 qa[8];
    #pragma unroll
    for (int i = 0; i < 8; i++) qa[i] = qp[i];

    float4 acc[8];
    #pragma unroll
    for (int i = 0; i < 8; i++) acc[i] = make_float4(0.f, 0.f, 0.f, 0.f);
    float m_run = 0.0f, l = 0.0f;

    for (int kt = 0; kt <= qt; kt++) {
        const float4* kp = (const float4*)(k + ((size_t)bh * T_SZ + kt * 64) * D_SZ);
        const float4* vp = (const float4*)(v + ((size_t)bh * T_SZ + kt * 64) * D_SZ);
        __syncthreads();
        #pragma unroll
        for (int i = 0; i < 8; i++) {
            Ks[tid + i * 64] = kp[tid + i * 64];
            Vs[tid + i * 64] = vp[tid + i * 64];
        }
        __syncthreads();

        int smax = (kt == qt) ? tid : 63;
        float tm = m_run;
        for (int s = 0; s <= smax; s++) {
            const float4* krow = &Ks[s * 8];
            float dot = 0.0f;
            #pragma unroll
            for (int i = 0; i < 8; i++) {
                float4 kk4 = krow[i];
                dot += qa[i].x * kk4.x + qa[i].y * kk4.y
                     + qa[i].z * kk4.z + qa[i].w * kk4.w;
            }
            float sc = dot * 0.0625f;
            tm = fmaxf(tm, sc);
            float p = __expf(sc - m_run);
            l += p;
            const float4* vrow = &Vs[s * 8];
            #pragma unroll
            for (int i = 0; i < 8; i++) {
                float4 vv = vrow[i];
                acc[i].x += p * vv.x;
                acc[i].y += p * vv.y;
                acc[i].z += p * vv.z;
                acc[i].w += p * vv.w;
            }
        }
        if (tm > m_run) {
            float corr = __expf(m_run - tm);
            l *= corr;
            #pragma unroll
            for (int i = 0; i < 8; i++) {
                acc[i].x *= corr; acc[i].y *= corr;
                acc[i].z *= corr; acc[i].w *= corr;
            }
            m_run = tm;
        }
    }

    float inv = __fdividef(1.0f, l);
    int bb = bh >> 3, hh = bh & 7;
    float4* op = (float4*)(out + ((size_t)(bb * T_SZ + t) * C_SZ + hh * D_SZ));
    #pragma unroll
    for (int i = 0; i < 8; i++) {
        float4 o;
        o.x = acc[i].x * inv; o.y = acc[i].y * inv;
        o.z = acc[i].z * inv; o.w = acc[i].w * inv;
        op[i] = o;
    }
}

// ---------------------------------------------------------------------------
extern "C" void kernel_launch(void* const* d_in, const int* in_sizes, int n_in,
                              void* d_out, int out_size) {
    (void)in_sizes; (void)n_in; (void)out_size;
    const float* x      = (const float*)d_in[0];
    const float* wq     = (const float*)d_in[1];
    const float* wk     = (const float*)d_in[2];
    const float* wv     = (const float*)d_in[3];
    const float* w_proj = (const float*)d_in[4];
    const float* b_proj = (const float*)d_in[5];
    const float* w1     = (const float*)d_in[6];
    const float* b1     = (const float*)d_in[7];
    const float* w2     = (const float*)d_in[8];
    const float* b2     = (const float*)d_in[9];
    const float* ln1_g  = (const float*)d_in[10];
    const float* ln1_b  = (const float*)d_in[11];
    const float* ln2_g  = (const float*)d_in[12];
    const float* ln2_b  = (const float*)d_in[13];
    float* out = (float*)d_out;

    float *h, *qb, *kb, *vb, *att, *x1, *h2, *f1;
    float *wqkvT, *wprojT, *w1T, *w2T;
    cudaGetSymbolAddress((void**)&h,   g_h);
    cudaGetSymbolAddress((void**)&qb,  g_q);
    cudaGetSymbolAddress((void**)&kb,  g_k);
    cudaGetSymbolAddress((void**)&vb,  g_v);
    cudaGetSymbolAddress((void**)&att, g_att);
    cudaGetSymbolAddress((void**)&x1,  g_x1);
    cudaGetSymbolAddress((void**)&h2,  g_h2);
    cudaGetSymbolAddress((void**)&f1,  g_f1);
    cudaGetSymbolAddress((void**)&wqkvT,  g_wqkvT);
    cudaGetSymbolAddress((void**)&wprojT, g_wprojT);
    cudaGetSymbolAddress((void**)&w1T,    g_w1T);
    cudaGetSymbolAddress((void**)&w2T,    g_w2T);

    // Weight packing / transposes (independent of activations)
    pack_qkv_kernel<<<768, 256>>>(wq, wk, wv, wqkvT);
    transpose_kernel<<<256, 256>>>(w_proj, wprojT, 256, 256);
    transpose_kernel<<<1024, 256>>>(w1, w1T, 256, 1024);
    transpose_kernel<<<1024, 256>>>(w2, w2T, 1024, 256);

    // 1. LN1
    ln_kernel<<<M_ROWS / 8, 256>>>(x, ln1_g, ln1_b, h);
    // 2. Fused QKV projection (N=768) -> scatter to [B,H,T,D]
    gemm_tc<0><<<dim3(768 / 128, M_ROWS / 128), 256>>>(h, wqkvT, nullptr, nullptr,
                                                       qb, kb, vb, 768, C_SZ);
    // 3. Causal flash attention -> [B,T,C]
    attn_kernel<<<dim3(T_SZ / 64, B_SZ * H_SZ), 64>>>(qb, kb, vb, att);
    // 4. Output projection + bias + residual
    gemm_tc<1><<<dim3(C_SZ / 128, M_ROWS / 128), 256>>>(att, wprojT, b_proj, x,
                                                        x1, nullptr, nullptr, C_SZ, C_SZ);
    // 5. LN2
    ln_kernel<<<M_ROWS / 8, 256>>>(x1, ln2_g, ln2_b, h2);
    // 6. FF1 + ReLU (N=1024)
    gemm_tc<2><<<dim3(FF_SZ / 128, M_ROWS / 128), 256>>>(h2, w1T, b1, nullptr,
                                                         f1, nullptr, nullptr, FF_SZ, C_SZ);
    // 7. FF2 + bias + residual -> out (K=1024)
    gemm_tc<1><<<dim3(C_SZ / 128, M_ROWS / 128), 256>>>(f1, w2T, b2, x1,
                                                        out, nullptr, nullptr, C_SZ, FF_SZ);
}

// round 5
// speedup vs baseline: 3.1559x; 1.8910x over previous
#include <cuda_runtime.h>
#include <cstdint>
#include <math.h>

// Problem constants
#define B_SZ   16
#define T_SZ   1024
#define C_SZ   256
#define H_SZ   8
#define D_SZ   32
#define M_ROWS (B_SZ * T_SZ)      // 16384
#define FF_SZ  (4 * C_SZ)         // 1024

// Scratch (allocation-free rule: __device__ globals)
__device__ float g_h  [M_ROWS * C_SZ];
__device__ float g_q  [M_ROWS * C_SZ];   // [B,H,T,D]
__device__ float g_k  [M_ROWS * C_SZ];
__device__ float g_v  [M_ROWS * C_SZ];
__device__ float g_att[M_ROWS * C_SZ];   // [B,T,C]
__device__ float g_x1 [M_ROWS * C_SZ];
__device__ float g_h2 [M_ROWS * C_SZ];
__device__ float g_f1 [M_ROWS * FF_SZ];
// Transposed (K-major) weights
__device__ float g_wqkvT[768 * 256];     // [n=3*256][k=256]
__device__ float g_wprojT[256 * 256];
__device__ float g_w1T  [1024 * 256];
__device__ float g_w2T  [256 * 1024];

// ---------------------------------------------------------------------------
// mma.sync tf32 helpers (plain sm_103-compatible PTX)
// ---------------------------------------------------------------------------
__device__ __forceinline__ uint32_t f2tf32(float x) {
    uint32_t r;
    asm("cvt.rna.tf32.f32 %0, %1;" : "=r"(r) : "f"(x));
    return r;
}
__device__ __forceinline__ void mma_tf32(float* d, const uint32_t* a, const uint32_t* b) {
    asm volatile(
        "mma.sync.aligned.m16n8k8.row.col.f32.tf32.tf32.f32 "
        "{%0,%1,%2,%3}, {%4,%5,%6,%7}, {%8,%9}, {%0,%1,%2,%3};\n"
        : "+f"(d[0]), "+f"(d[1]), "+f"(d[2]), "+f"(d[3])
        : "r"(a[0]), "r"(a[1]), "r"(a[2]), "r"(a[3]), "r"(b[0]), "r"(b[1]));
}

#define CP_ASYNC16(dst, src) \
    asm volatile("cp.async.ca.shared.global [%0], [%1], 16;" :: "r"(dst), "l"(src))
#define CP_COMMIT() asm volatile("cp.async.commit_group;" ::: "memory")
#define CP_WAIT1()  asm volatile("cp.async.wait_group 1;" ::: "memory")
#define CP_WAIT0()  asm volatile("cp.async.wait_group 0;" ::: "memory")

__device__ __forceinline__ uint32_t smem_u32(const void* p) {
    uint32_t a;
    asm("{ .reg .u64 t; cvta.to.shared.u64 t, %1; cvt.u32.u64 %0, t; }" : "=r"(a) : "l"(p));
    return a;
}

// ---------------------------------------------------------------------------
// LayerNorm: one warp per row of 256 floats
// ---------------------------------------------------------------------------
__global__ void ln_kernel(const float* __restrict__ x,
                          const float* __restrict__ g,
                          const float* __restrict__ b,
                          float* __restrict__ out) {
    int warp = threadIdx.x >> 5;
    int lane = threadIdx.x & 31;
    int row  = blockIdx.x * 8 + warp;

    const float4* xr = (const float4*)(x + (size_t)row * C_SZ);
    float4 v0 = xr[lane];
    float4 v1 = xr[lane + 32];

    float s  = v0.x + v0.y + v0.z + v0.w + v1.x + v1.y + v1.z + v1.w;
    float ss = v0.x*v0.x + v0.y*v0.y + v0.z*v0.z + v0.w*v0.w
             + v1.x*v1.x + v1.y*v1.y + v1.z*v1.z + v1.w*v1.w;

    #pragma unroll
    for (int o = 16; o; o >>= 1) {
        s  += __shfl_xor_sync(0xFFFFFFFFu, s,  o);
        ss += __shfl_xor_sync(0xFFFFFFFFu, ss, o);
    }
    float mu  = s * (1.0f / C_SZ);
    float var = ss * (1.0f / C_SZ) - mu * mu;
    float inv = rsqrtf(var + 1e-5f);

    const float4* gr = (const float4*)g;
    const float4* br = (const float4*)b;
    float4 g0 = gr[lane], g1 = gr[lane + 32];
    float4 b0 = br[lane], b1 = br[lane + 32];

    float4 o0, o1;
    o0.x = (v0.x - mu) * inv * g0.x + b0.x;
    o0.y = (v0.y - mu) * inv * g0.y + b0.y;
    o0.z = (v0.z - mu) * inv * g0.z + b0.z;
    o0.w = (v0.w - mu) * inv * g0.w + b0.w;
    o1.x = (v1.x - mu) * inv * g1.x + b1.x;
    o1.y = (v1.y - mu) * inv * g1.y + b1.y;
    o1.z = (v1.z - mu) * inv * g1.z + b1.z;
    o1.w = (v1.w - mu) * inv * g1.w + b1.w;

    float4* orow = (float4*)(out + (size_t)row * C_SZ);
    orow[lane]      = o0;
    orow[lane + 32] = o1;
}

// ---------------------------------------------------------------------------
// Tiled transposes (coalesced both sides)
// ---------------------------------------------------------------------------
__global__ void transpose_tiled(const float* __restrict__ in, float* __restrict__ outT,
                                int rows, int cols) {
    // in: [rows][cols] -> outT: [cols][rows]; rows, cols multiples of 32
    __shared__ float tile[32][33];
    int bx = blockIdx.x * 32, by = blockIdx.y * 32;
    int tx = threadIdx.x, ty = threadIdx.y;   // block (32, 8)
    #pragma unroll
    for (int e = 0; e < 4; e++)
        tile[ty + e*8][tx] = in[(size_t)(by + ty + e*8) * cols + bx + tx];
    __syncthreads();
    #pragma unroll
    for (int e = 0; e < 4; e++)
        outT[(size_t)(bx + ty + e*8) * rows + by + tx] = tile[tx][ty + e*8];
}

__global__ void pack_qkv_tiled(const float* __restrict__ wq, const float* __restrict__ wk,
                               const float* __restrict__ wv, float* __restrict__ outT) {
    // w: [8 h][256 c][32 d] -> outT[(sel*256 + h*32 + d)][c]
    __shared__ float tile[32][33];
    int h   = blockIdx.y;
    int sel = blockIdx.z;
    int cb  = blockIdx.x * 32;
    const float* w = (sel == 0) ? wq : (sel == 1) ? wk : wv;
    const float* src = w + h * (C_SZ * D_SZ);
    int tx = threadIdx.x, ty = threadIdx.y;
    #pragma unroll
    for (int e = 0; e < 4; e++)
        tile[ty + e*8][tx] = src[(cb + ty + e*8) * D_SZ + tx];
    __syncthreads();
    #pragma unroll
    for (int e = 0; e < 4; e++) {
        int d = ty + e*8;
        outT[(size_t)(sel*256 + h*32 + d) * C_SZ + cb + tx] = tile[tx][d];
    }
}

// ---------------------------------------------------------------------------
// tf32 HMMA GEMM with cp.async double buffering.
// C[M, Ntot] = A[M, K] @ BwT[Ntot, K]^T;  BM=128 BN=128 BK=16, 256 thr.
// MODE 0: scatter to q/k/v [B,H,T,D];  MODE 1: +bias+res;  MODE 2: relu(+bias)
// ---------------------------------------------------------------------------
#define PAD 20

template <int MODE>
__global__ __launch_bounds__(256)
void gemm_tc(const float* __restrict__ A, const float* __restrict__ Bw,
             const float* __restrict__ bias, const float* __restrict__ res,
             float* __restrict__ out, float* __restrict__ out2, float* __restrict__ out3,
             int Ntot, int K) {
    __shared__ float As[2][128][PAD];
    __shared__ float Bs[2][128][PAD];

    const int tid  = threadIdx.x;
    const int wid  = tid >> 5;
    const int lane = tid & 31;
    const int g    = lane >> 2;
    const int tg   = lane & 3;
    const int wm   = wid & 1;
    const int wn   = wid >> 1;
    const int m0   = blockIdx.y * 128;
    const int n0   = blockIdx.x * 128;

    const int lrow0 = tid >> 2;
    const int lrow1 = lrow0 + 64;
    const int lc4   = (tid & 3) * 4;

    float acc[4][4][4];
    #pragma unroll
    for (int i = 0; i < 4; i++)
        #pragma unroll
        for (int j = 0; j < 4; j++)
            #pragma unroll
            for (int r = 0; r < 4; r++) acc[i][j][r] = 0.0f;

    const int nchunks = K >> 4;

    const float* gA0 = A  + (size_t)(m0 + lrow0) * K + lc4;
    const float* gA1 = A  + (size_t)(m0 + lrow1) * K + lc4;
    const float* gB0 = Bw + (size_t)(n0 + lrow0) * K + lc4;
    const float* gB1 = Bw + (size_t)(n0 + lrow1) * K + lc4;

    // prologue: stage 0
    {
        CP_ASYNC16(smem_u32(&As[0][lrow0][lc4]), gA0);
        CP_ASYNC16(smem_u32(&As[0][lrow1][lc4]), gA1);
        CP_ASYNC16(smem_u32(&Bs[0][lrow0][lc4]), gB0);
        CP_ASYNC16(smem_u32(&Bs[0][lrow1][lc4]), gB1);
        CP_COMMIT();
    }

    for (int c = 0; c < nchunks; c++) {
        if (c + 1 < nchunks) {
            const int st = (c + 1) & 1;
            const int k0 = (c + 1) << 4;
            CP_ASYNC16(smem_u32(&As[st][lrow0][lc4]), gA0 + k0);
            CP_ASYNC16(smem_u32(&As[st][lrow1][lc4]), gA1 + k0);
            CP_ASYNC16(smem_u32(&Bs[st][lrow0][lc4]), gB0 + k0);
            CP_ASYNC16(smem_u32(&Bs[st][lrow1][lc4]), gB1 + k0);
            CP_COMMIT();
            CP_WAIT1();
        } else {
            CP_WAIT0();
        }
        __syncthreads();
        const int st = c & 1;

        #pragma unroll
        for (int kk = 0; kk < 16; kk += 8) {
            uint32_t af[4][4], bf[4][2];
            #pragma unroll
            for (int i = 0; i < 4; i++) {
                int r0 = wm * 64 + i * 16 + g;
                af[i][0] = f2tf32(As[st][r0    ][kk + tg]);
                af[i][1] = f2tf32(As[st][r0 + 8][kk + tg]);
                af[i][2] = f2tf32(As[st][r0    ][kk + tg + 4]);
                af[i][3] = f2tf32(As[st][r0 + 8][kk + tg + 4]);
            }
            #pragma unroll
            for (int j = 0; j < 4; j++) {
                int n = wn * 32 + j * 8 + g;
                bf[j][0] = f2tf32(Bs[st][n][kk + tg]);
                bf[j][1] = f2tf32(Bs[st][n][kk + tg + 4]);
            }
            #pragma unroll
            for (int i = 0; i < 4; i++)
                #pragma unroll
                for (int j = 0; j < 4; j++)
                    mma_tf32(acc[i][j], af[i], bf[j]);
        }
        __syncthreads();
    }

    // ---- epilogue ----
    #pragma unroll
    for (int i = 0; i < 4; i++) {
        #pragma unroll
        for (int half = 0; half < 2; half++) {
            int m  = m0 + wm * 64 + i * 16 + g + half * 8;
            int bb = m >> 10, t = m & 1023;
            #pragma unroll
            for (int j = 0; j < 4; j++) {
                int col = n0 + wn * 32 + j * 8 + tg * 2;
                float2 vv = make_float2(acc[i][j][half * 2], acc[i][j][half * 2 + 1]);
                if (MODE == 0) {
                    int tsel = col >> 8;
                    int c2 = col & 255;
                    int hh = c2 >> 5, d = c2 & 31;
                    float* dst = (tsel == 0) ? out : (tsel == 1) ? out2 : out3;
                    *(float2*)(dst + (((size_t)(bb * H_SZ + hh) * T_SZ + t) * D_SZ + d)) = vv;
                } else if (MODE == 1) {
                    float2 bz = *(const float2*)(bias + col);
                    float2 rr = *(const float2*)(res + (size_t)m * Ntot + col);
                    vv.x += bz.x + rr.x; vv.y += bz.y + rr.y;
                    *(float2*)(out + (size_t)m * Ntot + col) = vv;
                } else {
                    float2 bz = *(const float2*)(bias + col);
                    vv.x = fmaxf(vv.x + bz.x, 0.0f);
                    vv.y = fmaxf(vv.y + bz.y, 0.0f);
                    *(float2*)(out + (size_t)m * Ntot + col) = vv;
                }
            }
        }
    }
}

// ---------------------------------------------------------------------------
// Tensor-core flash attention (causal, tf32 mma, fp32 softmax/accum).
// Block: 128 threads (4 warps), 128 queries; K-tiles of 64 keys.
// q,k,v: [B,H,T,D]; out: [B,T,C] heads concatenated. Scale 1/16 folded into Q.
// SMEM: Ks (64x36) aliased with per-warp P tiles (4x32x68); Vt (32x68).
// ---------------------------------------------------------------------------
#define PS_STRIDE 68
#define KS_STRIDE 36
#define VT_STRIDE 68
#define SM_PS_BYTES (4 * 32 * PS_STRIDE * 4)   // 34816 (covers Ks' 9216)
#define SM_VT_OFF   SM_PS_BYTES

__global__ __launch_bounds__(128)
void attn_mma(const float* __restrict__ q, const float* __restrict__ k,
              const float* __restrict__ v, float* __restrict__ out) {
    __shared__ __align__(16) unsigned char sm[SM_PS_BYTES + 32 * VT_STRIDE * 4];
    uint32_t (*Ks)[KS_STRIDE] = (uint32_t(*)[KS_STRIDE])sm;
    uint32_t (*Vt)[VT_STRIDE] = (uint32_t(*)[VT_STRIDE])(sm + SM_VT_OFF);

    const int tid  = threadIdx.x;
    const int wq_  = tid >> 5;
    const int lane = tid & 31;
    const int g    = lane >> 2;
    const int tg   = lane & 3;
    const int qt   = blockIdx.x;
    const int bh   = blockIdx.y;
    const int q0   = qt * 128;
    const int qw   = q0 + wq_ * 32;

    uint32_t (*Pw)[PS_STRIDE] = (uint32_t(*)[PS_STRIDE])(sm + (size_t)wq_ * 32 * PS_STRIDE * 4);

    const float* qbase = q + ((size_t)bh << 10) * D_SZ;
    const float* kbase = k + ((size_t)bh << 10) * D_SZ;
    const float* vbase = v + ((size_t)bh << 10) * D_SZ;

    // Q fragments (scale 1/16 folded in)
    uint32_t qa[2][4][4];
    #pragma unroll
    for (int i = 0; i < 2; i++)
        #pragma unroll
        for (int kc = 0; kc < 4; kc++) {
            int r0 = qw + 16 * i + g;
            int c0 = kc * 8 + tg;
            qa[i][kc][0] = f2tf32(0.0625f * qbase[(size_t)r0 * 32 + c0]);
            qa[i][kc][1] = f2tf32(0.0625f * qbase[(size_t)(r0 + 8) * 32 + c0]);
            qa[i][kc][2] = f2tf32(0.0625f * qbase[(size_t)r0 * 32 + c0 + 4]);
            qa[i][kc][3] = f2tf32(0.0625f * qbase[(size_t)(r0 + 8) * 32 + c0 + 4]);
        }

    float o_[2][4][4];
    #pragma unroll
    for (int i = 0; i < 2; i++)
        #pragma unroll
        for (int j = 0; j < 4; j++)
            #pragma unroll
            for (int r = 0; r < 4; r++) o_[i][j][r] = 0.0f;
    float m_[2][2] = {{0.f, 0.f}, {0.f, 0.f}};
    float l_[2][2] = {{0.f, 0.f}, {0.f, 0.f}};

    // V transpose-load mapping: warp-local (d_in, s_in), d block per warp
    const int v_d  = (tid >> 5) * 8 + (lane & 7);
    const int v_si = lane >> 3;

    const int nkt = 2 * qt + 2;
    for (int ktile = 0; ktile < nkt; ktile++) {
        const int s0 = ktile * 64;
        __syncthreads();
        // K tile: [64 s][32 d] tf32, 4 float4 per thread
        #pragma unroll
        for (int e = 0; e < 4; e++) {
            int n  = tid + (e << 7);
            int s  = n >> 3, c4 = (n & 7) << 2;
            float4 kv = *(const float4*)(kbase + (size_t)(s0 + s) * 32 + c4);
            uint4 kc4 = make_uint4(f2tf32(kv.x), f2tf32(kv.y), f2tf32(kv.z), f2tf32(kv.w));
            *(uint4*)&Ks[s][c4] = kc4;
        }
        // V tile transposed: Vt[d][s]
        #pragma unroll
        for (int it = 0; it < 16; it++) {
            int s = v_si + (it << 2);
            Vt[v_d][s] = f2tf32(vbase[(size_t)(s0 + s) * 32 + v_d]);
        }
        __syncthreads();

        const bool active = (s0 <= qw + 31);
        float S[2][8][4];

        if (active) {
            #pragma unroll
            for (int i = 0; i < 2; i++)
                #pragma unroll
                for (int j = 0; j < 8; j++)
                    #pragma unroll
                    for (int r = 0; r < 4; r++) S[i][j][r] = 0.0f;

            // S = Q K^T
            #pragma unroll
            for (int kc = 0; kc < 4; kc++) {
                uint32_t bf[8][2];
                #pragma unroll
                for (int j = 0; j < 8; j++) {
                    bf[j][0] = Ks[j * 8 + g][kc * 8 + tg];
                    bf[j][1] = Ks[j * 8 + g][kc * 8 + tg + 4];
                }
                #pragma unroll
                for (int i = 0; i < 2; i++)
                    #pragma unroll
                    for (int j = 0; j < 8; j++)
                        mma_tf32(S[i][j], qa[i][kc], bf[j]);
            }
            // causal mask (tiles crossing the diagonal)
            if (s0 + 63 > qw) {
                #pragma unroll
                for (int i = 0; i < 2; i++)
                    #pragma unroll
                    for (int h = 0; h < 2; h++) {
                        int qrow = qw + 16 * i + g + 8 * h;
                        #pragma unroll
                        for (int j = 0; j < 8; j++) {
                            int sc = s0 + j * 8 + 2 * tg;
                            if (sc > qrow)     S[i][j][2 * h]     = -1e30f;
                            if (sc + 1 > qrow) S[i][j][2 * h + 1] = -1e30f;
                        }
                    }
            }
            // online softmax
            #pragma unroll
            for (int i = 0; i < 2; i++)
                #pragma unroll
                for (int h = 0; h < 2; h++) {
                    float mx = m_[i][h];
                    #pragma unroll
                    for (int j = 0; j < 8; j++) {
                        mx = fmaxf(mx, S[i][j][2 * h]);
                        mx = fmaxf(mx, S[i][j][2 * h + 1]);
                    }
                    mx = fmaxf(mx, __shfl_xor_sync(0xFFFFFFFFu, mx, 1));
                    mx = fmaxf(mx, __shfl_xor_sync(0xFFFFFFFFu, mx, 2));
                    float corr = __expf(m_[i][h] - mx);
                    m_[i][h] = mx;
                    float sum = 0.0f;
                    #pragma unroll
                    for (int j = 0; j < 8; j++) {
                        float p0 = __expf(S[i][j][2 * h] - mx);
                        float p1 = __expf(S[i][j][2 * h + 1] - mx);
                        S[i][j][2 * h] = p0; S[i][j][2 * h + 1] = p1;
                        sum += p0 + p1;
                    }
                    sum += __shfl_xor_sync(0xFFFFFFFFu, sum, 1);
                    sum += __shfl_xor_sync(0xFFFFFFFFu, sum, 2);
                    l_[i][h] = l_[i][h] * corr + sum;
                    #pragma unroll
                    for (int jn = 0; jn < 4; jn++) {
                        o_[i][jn][2 * h]     *= corr;
                        o_[i][jn][2 * h + 1] *= corr;
                    }
                }
        }

        __syncthreads();   // Ks reads done before P overwrites the aliased region

        if (active) {
            // store P (tf32) to per-warp SMEM
            #pragma unroll
            for (int i = 0; i < 2; i++)
                #pragma unroll
                for (int h = 0; h < 2; h++) {
                    int row = 16 * i + g + 8 * h;
                    #pragma unroll
                    for (int j = 0; j < 8; j++) {
                        uint2 pp = make_uint2(f2tf32(S[i][j][2 * h]),
                                              f2tf32(S[i][j][2 * h + 1]));
                        *(uint2*)&Pw[row][j * 8 + 2 * tg] = pp;
                    }
                }
            __syncwarp();
            // O += P V
            #pragma unroll
            for (int kf = 0; kf < 8; kf++) {
                uint32_t pa[2][4], vb[4][2];
                #pragma unroll
                for (int i = 0; i < 2; i++) {
                    pa[i][0] = Pw[16 * i + g    ][kf * 8 + tg];
                    pa[i][1] = Pw[16 * i + 8 + g][kf * 8 + tg];
                    pa[i][2] = Pw[16 * i + g    ][kf * 8 + tg + 4];
                    pa[i][3] = Pw[16 * i + 8 + g][kf * 8 + tg + 4];
                }
                #pragma unroll
                for (int jn = 0; jn < 4; jn++) {
                    vb[jn][0] = Vt[jn * 8 + g][kf * 8 + tg];
                    vb[jn][1] = Vt[jn * 8 + g][kf * 8 + tg + 4];
                }
                #pragma unroll
                for (int i = 0; i < 2; i++)
                    #pragma unroll
                    for (int jn = 0; jn < 4; jn++)
                        mma_tf32(o_[i][jn], pa[i], vb[jn]);
            }
        }
    }

    // epilogue -> out[B,T,C] heads concat
    const int bb = bh >> 3, hh = bh & 7;
    #pragma unroll
    for (int i = 0; i < 2; i++)
        #pragma unroll
        for (int h = 0; h < 2; h++) {
            int trow = q0 + wq_ * 32 + 16 * i + g + 8 * h;
            float nv = 1.0f / l_[i][h];
            #pragma unroll
            for (int jn = 0; jn < 4; jn++) {
                float2 ov = make_float2(o_[i][jn][2 * h] * nv, o_[i][jn][2 * h + 1] * nv);
                int col = jn * 8 + 2 * tg;
                *(float2*)(out + ((size_t)((bb << 10) + trow) * C_SZ + hh * 32 + col)) = ov;
            }
        }
}

// ---------------------------------------------------------------------------
extern "C" void kernel_launch(void* const* d_in, const int* in_sizes, int n_in,
                              void* d_out, int out_size) {
    (void)in_sizes; (void)n_in; (void)out_size;
    const float* x      = (const float*)d_in[0];
    const float* wq     = (const float*)d_in[1];
    const float* wk     = (const float*)d_in[2];
    const float* wv     = (const float*)d_in[3];
    const float* w_proj = (const float*)d_in[4];
    const float* b_proj = (const float*)d_in[5];
    const float* w1     = (const float*)d_in[6];
    const float* b1     = (const float*)d_in[7];
    const float* w2     = (const float*)d_in[8];
    const float* b2     = (const float*)d_in[9];
    const float* ln1_g  = (const float*)d_in[10];
    const float* ln1_b  = (const float*)d_in[11];
    const float* ln2_g  = (const float*)d_in[12];
    const float* ln2_b  = (const float*)d_in[13];
    float* out = (float*)d_out;

    float *h, *qb, *kb, *vb, *att, *x1, *h2, *f1;
    float *wqkvT, *wprojT, *w1T, *w2T;
    cudaGetSymbolAddress((void**)&h,   g_h);
    cudaGetSymbolAddress((void**)&qb,  g_q);
    cudaGetSymbolAddress((void**)&kb,  g_k);
    cudaGetSymbolAddress((void**)&vb,  g_v);
    cudaGetSymbolAddress((void**)&att, g_att);
    cudaGetSymbolAddress((void**)&x1,  g_x1);
    cudaGetSymbolAddress((void**)&h2,  g_h2);
    cudaGetSymbolAddress((void**)&f1,  g_f1);
    cudaGetSymbolAddress((void**)&wqkvT,  g_wqkvT);
    cudaGetSymbolAddress((void**)&wprojT, g_wprojT);
    cudaGetSymbolAddress((void**)&w1T,    g_w1T);
    cudaGetSymbolAddress((void**)&w2T,    g_w2T);

    // Weight packing / transposes (tiled, coalesced)
    pack_qkv_tiled<<<dim3(8, 8, 3), dim3(32, 8)>>>(wq, wk, wv, wqkvT);
    transpose_tiled<<<dim3(8, 8),   dim3(32, 8)>>>(w_proj, wprojT, 256, 256);
    transpose_tiled<<<dim3(32, 8),  dim3(32, 8)>>>(w1, w1T, 256, 1024);
    transpose_tiled<<<dim3(8, 32),  dim3(32, 8)>>>(w2, w2T, 1024, 256);

    // 1. LN1
    ln_kernel<<<M_ROWS / 8, 256>>>(x, ln1_g, ln1_b, h);
    // 2. Fused QKV projection (N=768) -> scatter to [B,H,T,D]
    gemm_tc<0><<<dim3(768 / 128, M_ROWS / 128), 256>>>(h, wqkvT, nullptr, nullptr,
                                                       qb, kb, vb, 768, C_SZ);
    // 3. Causal flash attention (tensor cores) -> [B,T,C]
    attn_mma<<<dim3(T_SZ / 128, B_SZ * H_SZ), 128>>>(qb, kb, vb, att);
    // 4. Output projection + bias + residual
    gemm_tc<1><<<dim3(C_SZ / 128, M_ROWS / 128), 256>>>(att, wprojT, b_proj, x,
                                                        x1, nullptr, nullptr, C_SZ, C_SZ);
    // 5. LN2
    ln_kernel<<<M_ROWS / 8, 256>>>(x1, ln2_g, ln2_b, h2);
    // 6. FF1 + ReLU (N=1024)
    gemm_tc<2><<<dim3(FF_SZ / 128, M_ROWS / 128), 256>>>(h2, w1T, b1, nullptr,
                                                         f1, nullptr, nullptr, FF_SZ, C_SZ);
    // 7. FF2 + bias + residual -> out (K=1024)
    gemm_tc<1><<<dim3(C_SZ / 128, M_ROWS / 128), 256>>>(f1, w2T, b2, x1,
                                                        out, nullptr, nullptr, C_SZ, FF_SZ);
}